// round 16
// baseline (speedup 1.0000x reference)
#include <cuda_runtime.h>
#include <stdint.h>

// Problem constants
#define B_    256
#define L_    128
#define NTHR  256
#define NBLK  128     // 16 row-groups x 8 col-groups

// Shared memory layout (float offsets)
#define OFF_WL  0
#define OFF_WR  10560                  // 80 x 132
#define OFF_SH  21120                  // 16 x 132
#define OFF_SX  23232                  // 2 x 16 x 132
#define SZ_SX   2112
#define OFF_ZB  27456                  // 8 k-splits x 16 x 84
#define SZ_ZB   (16*84)
#define SMEM_FLOATS (OFF_ZB + 8*SZ_ZB) // 38208
#define SMEM_BYTES  (SMEM_FLOATS*4)    // 152832 B -> 1 CTA/SM

// Cross-block state. g_h layout: [buf][batch_row*128 + k]
__device__ float    g_h[2][B_ * 128];
__device__ unsigned g_bar[16 * 64];    // per-rg counters, 256B stride
__device__ unsigned g_done[16 * 64];

__device__ __forceinline__ unsigned long long fma2(unsigned long long a,
                                                   unsigned long long b,
                                                   unsigned long long c) {
    unsigned long long d;
    asm("fma.rn.f32x2 %0, %1, %2, %3;" : "=l"(d) : "l"(a), "l"(b), "l"(c));
    return d;
}
__device__ __forceinline__ float hadd2(unsigned long long a) {
    float lo, hi;
    asm("mov.b64 {%0, %1}, %2;" : "=f"(lo), "=f"(hi) : "l"(a));
    return lo + hi;
}
__device__ __forceinline__ float tanh_hw(float x) {
    float y;
    asm("tanh.approx.f32 %0, %1;" : "=f"(y) : "f"(x));
    return y;
}
__device__ __forceinline__ float sigm(float x) {
    return fmaf(0.5f, tanh_hw(0.5f * x), 0.5f);
}

// acc[g][r] += W(5 gate-rows, 16 k's) . X(8 rows, 16 k's)
__device__ __forceinline__ void gemm_sideB(const float* __restrict__ wbase,
                                           const float* __restrict__ hbase,
                                           unsigned long long acc[5][8]) {
    const ulonglong2* W = (const ulonglong2*)wbase;
    const ulonglong2* H = (const ulonglong2*)hbase;
#pragma unroll
    for (int kq = 0; kq < 4; kq++) {
        ulonglong2 h[8];
#pragma unroll
        for (int r = 0; r < 8; r++) h[r] = H[r * 33 + kq];
#pragma unroll
        for (int g = 0; g < 5; g++) {
            ulonglong2 w = W[g * 33 + kq];
#pragma unroll
            for (int r = 0; r < 8; r++) {
                acc[g][r] = fma2(w.x, h[r].x, acc[g][r]);
                acc[g][r] = fma2(w.y, h[r].y, acc[g][r]);
            }
        }
    }
}

extern "C" __global__ void __launch_bounds__(NTHR, 1)
tac_lstm16(const int*   __restrict__ ids,
           const float* __restrict__ embed,
           const float* __restrict__ whx_w,
           const float* __restrict__ whx_b,
           const float* __restrict__ init_state,
           const float* __restrict__ final_w,
           const float* __restrict__ final_b,
           float*       __restrict__ out)
{
    extern __shared__ float sm[];
    const int tid = threadIdx.x;
    const int bid = blockIdx.x;
    const int cg  = bid & 7;
    const int rg  = bid >> 3;
    const int colbase = cg * 16;
    const int rowbase = rg * 16;

    unsigned* bar  = &g_bar[rg << 6];
    unsigned* done = &g_done[rg << 6];

    // GEMM identity: 16 cols x 2 rowgroups(8 rows) x 8 k-splits(16 k)
    const int col    = tid & 15;
    const int rowgrp = (tid >> 4) & 1;
    const int ks     = tid >> 5;          // warp id
    const int kb     = ks << 4;
    const int r0     = rowgrp << 3;

    // gate identity: gcol fastest (coalesced h stores)
    const int gcol = tid & 15;
    const int grow = tid >> 4;

    // ---- one-time: weights into smem ----
    for (int idx = tid; idx < 80 * 128; idx += NTHR) {
        int k  = idx & 127;
        int j2 = idx >> 7;                 // c*5+g
        int c  = j2 / 5;
        int g  = j2 - 5 * c;
        int jg = (g << 7) + colbase + c;
        sm[OFF_WL + j2 * 132 + k] = whx_w[jg * 256 + k];
        sm[OFF_WR + j2 * 132 + k] = whx_w[jg * 256 + 128 + k];
    }
    // SH(t=0) = init_state broadcast over rows
    for (int idx = tid; idx < 16 * 128; idx += NTHR) {
        int r = idx >> 7, k = idx & 127;
        sm[OFF_SH + r * 132 + k] = init_state[k];
    }
    // gather x(0) -> SX[0], x(1) -> SX[1]
    {
        int r = tid >> 4, l = tid & 15;
#pragma unroll
        for (int tt = 0; tt < 2; tt++) {
            int id = __ldg(&ids[(rowbase + r) * L_ + tt]);
            const float4* eb = (const float4*)(embed + (size_t)id * 256);
            float4 e0 = __ldg(eb + l);
            float4 e1 = __ldg(eb + 16 + l);
            *(float4*)&sm[OFF_SX + tt * SZ_SX + r * 132 + l * 4]      = e0;
            *(float4*)&sm[OFF_SX + tt * SZ_SX + r * 132 + 64 + l * 4] = e1;
        }
    }
    float cstate = init_state[128 + colbase + gcol];
    int   id0    = __ldg(&ids[(rowbase + grow) * L_]);
    float rc_cur = __ldg(&embed[(size_t)id0 * 256 + 128 + colbase + gcol]);
    float rc_next = 0.0f;
    float bia[5];
#pragma unroll
    for (int g = 0; g < 5; g++)
        bia[g] = whx_b[(g << 7) + colbase + gcol];
    __syncthreads();

    const float* wlq = sm + OFF_WL + col * 5 * 132 + kb;
    const float* wrq = sm + OFF_WR + col * 5 * 132 + kb;
    const int    xro = r0 * 132 + kb;

    unsigned long long acc[5][8];
#pragma unroll
    for (int g = 0; g < 5; g++)
#pragma unroll
        for (int r = 0; r < 8; r++) acc[g][r] = 0ull;

    // accR(0) from SX[0]
    gemm_sideB(wrq, sm + OFF_SX + xro, acc);

    // ================= sequential scan =================
    for (int t = 0; t < L_; t++) {
        // ---- load h(t) tile (t>0): [b][k] layout ----
        if (t > 0) {
            const float4* hb = (const float4*)(g_h[t & 1] + rowbase * 128);
            {
                int r  = tid >> 5;             // warp id = row
                int k4 = tid & 31;
                float4 v = __ldcg(hb + r * 32 + k4);
                *(float4*)&sm[OFF_SH + r * 132 + k4 * 4] = v;
                float4 w = __ldcg(hb + (r + 8) * 32 + k4);
                *(float4*)&sm[OFF_SH + (r + 8) * 132 + k4 * 4] = w;
            }
            __syncthreads();
        }

        // ---- accL(t) on top of accR(t) ----
        gemm_sideB(wlq, sm + OFF_SH + xro, acc);

        // ---- store z partials (stride 5 mod 32 -> conflict-free) ----
        {
            float* zb = sm + OFF_ZB + ks * SZ_ZB + col * 5;
#pragma unroll
            for (int g = 0; g < 5; g++)
#pragma unroll
                for (int r = 0; r < 8; r++)
                    zb[(r0 + r) * 84 + g] = hadd2(acc[g][r]);
        }
        __syncthreads();

        // ---- gate phase: reduce 8 k-split partials (bias in registers) ----
        {
            const float* z0 = sm + OFF_ZB + grow * 84 + gcol * 5;
            float z[5];
#pragma unroll
            for (int g = 0; g < 5; g++) {
                float s = bia[g];
#pragma unroll
                for (int p = 0; p < 8; p++) s += z0[p * SZ_ZB + g];
                z[g] = s;
            }
            float ta  = tanh_hw(z[0]);
            float si  = sigm(z[1]);
            float sf1 = sigm(z[2]);
            float sf2 = sigm(z[3]);
            float so  = sigm(z[4]);
            cstate = ta * si + sf1 * cstate + sf2 * rc_cur;
            float hval = so * tanh_hw(cstate);
            __stcg(&g_h[(t + 1) & 1][(rowbase + grow) * 128 + colbase + gcol], hval);
        }

        __syncthreads();
        if (tid == 0)
            asm volatile("red.release.gpu.global.add.u32 [%0], %1;"
                         :: "l"(bar), "r"(1u) : "memory");

        // ---- shadow: right GEMM for t+1, gather x(t+2), rc(t+1) ----
#pragma unroll
        for (int g = 0; g < 5; g++)
#pragma unroll
            for (int r = 0; r < 8; r++) acc[g][r] = 0ull;

        if (t < L_ - 1) {
            int idn = __ldg(&ids[(rowbase + grow) * L_ + t + 1]);
            rc_next = __ldg(&embed[(size_t)idn * 256 + 128 + colbase + gcol]);
            gemm_sideB(wrq, sm + OFF_SX + ((t + 1) & 1) * SZ_SX + xro, acc);
        }
        if (t < L_ - 2) {
            int r = tid >> 4, l = tid & 15;
            int id = __ldg(&ids[(rowbase + r) * L_ + t + 2]);
            const float4* eb = (const float4*)(embed + (size_t)id * 256);
            float4 e0 = __ldg(eb + l);
            float4 e1 = __ldg(eb + 16 + l);
            *(float4*)&sm[OFF_SX + (t & 1) * SZ_SX + r * 132 + l * 4]      = e0;
            *(float4*)&sm[OFF_SX + (t & 1) * SZ_SX + r * 132 + 64 + l * 4] = e1;
        }

        // ---- all threads poll (identical addr -> one L2 req/warp) ----
        {
            unsigned tgt = 8u * (unsigned)(t + 1);
            unsigned v;
            do {
                asm volatile("ld.acquire.gpu.global.u32 %0, [%1];"
                             : "=r"(v) : "l"(bar) : "memory");
            } while (v < tgt);
        }
        rc_cur = rc_next;
    }

    // ================= final projection (cg==0 blocks) =================
    if (cg == 0) {
        int r2 = tid >> 4;
        int l2 = tid & 15;
        const float* hrow = g_h[0] + (rowbase + r2) * 128;
        float p0 = 0.f, p1 = 0.f, p2 = 0.f;
#pragma unroll
        for (int i = 0; i < 8; i++) {
            int k = l2 * 8 + i;
            float hv = __ldcg(&hrow[k]);
            p0 = fmaf(hv, __ldg(&final_w[k]),       p0);
            p1 = fmaf(hv, __ldg(&final_w[128 + k]), p1);
            p2 = fmaf(hv, __ldg(&final_w[256 + k]), p2);
        }
#pragma unroll
        for (int off = 8; off > 0; off >>= 1) {
            p0 += __shfl_down_sync(0xffffffffu, p0, off, 16);
            p1 += __shfl_down_sync(0xffffffffu, p1, off, 16);
            p2 += __shfl_down_sync(0xffffffffu, p2, off, 16);
        }
        if (l2 == 0) {
            int b = rowbase + r2;
            out[b * 3 + 0] = p0 + __ldg(&final_b[0]);
            out[b * 3 + 1] = p1 + __ldg(&final_b[1]);
            out[b * 3 + 2] = p2 + __ldg(&final_b[2]);
        }
    }

    // ---- reset this rg's counters for next graph replay ----
    __threadfence();
    __syncthreads();
    if (tid == 0) {
        unsigned v = atomicAdd(done, 1u);
        if (v == 7u) {
            *bar  = 0u;
            *done = 0u;
            __threadfence();
        }
    }
}

extern "C" void kernel_launch(void* const* d_in, const int* in_sizes, int n_in,
                              void* d_out, int out_size)
{
    const int*   ids        = nullptr;
    const float* embed      = nullptr;
    const float* whx_w      = nullptr;
    const float* whx_b      = nullptr;
    const float* init_state = nullptr;
    const float* final_w    = nullptr;
    const float* final_b    = nullptr;
    for (int i = 0; i < n_in; i++) {
        switch (in_sizes[i]) {
            case 256 * 128:   ids        = (const int*)d_in[i];   break;
            case 50000 * 256: embed      = (const float*)d_in[i]; break;
            case 640 * 256:   whx_w      = (const float*)d_in[i]; break;
            case 640:         whx_b      = (const float*)d_in[i]; break;
            case 256:         init_state = (const float*)d_in[i]; break;
            case 3 * 128:     final_w    = (const float*)d_in[i]; break;
            case 3:           final_b    = (const float*)d_in[i]; break;
            default: break;
        }
    }
    float* out = (float*)d_out;

    cudaFuncSetAttribute(tac_lstm16,
                         cudaFuncAttributeMaxDynamicSharedMemorySize, SMEM_BYTES);
    tac_lstm16<<<NBLK, NTHR, SMEM_BYTES>>>(ids, embed, whx_w, whx_b,
                                           init_state, final_w, final_b, out);
}

// round 17
// speedup vs baseline: 1.0573x; 1.0573x over previous
#include <cuda_runtime.h>
#include <stdint.h>

// Problem constants
#define B_    256
#define L_    128
#define NTHR  256
#define NBLK  128     // 16 row-groups x 8 col-groups

// Shared memory layout (float offsets)
#define OFF_WL  0
#define OFF_WR  10560                  // 80 x 132
#define OFF_SH  21120                  // 16 x 132
#define OFF_SX  23232                  // 2 x 16 x 132
#define SZ_SX   2112
#define OFF_ZB  27456                  // 8 k-splits x 16 x 84
#define SZ_ZB   (16*84)
#define OFF_SB  38208                  // 80
#define SMEM_FLOATS 38288
#define SMEM_BYTES  (SMEM_FLOATS*4)    // 153152 B -> 1 CTA/SM

// Cross-block state. g_h layout: [buf][batch_row*128 + k]
__device__ float    g_h[2][B_ * 128];
__device__ unsigned g_bar[16 * 64];    // per-rg counters, 256B stride
__device__ unsigned g_done[16 * 64];

__device__ __forceinline__ unsigned long long fma2(unsigned long long a,
                                                   unsigned long long b,
                                                   unsigned long long c) {
    unsigned long long d;
    asm("fma.rn.f32x2 %0, %1, %2, %3;" : "=l"(d) : "l"(a), "l"(b), "l"(c));
    return d;
}
__device__ __forceinline__ float hadd2(unsigned long long a) {
    float lo, hi;
    asm("mov.b64 {%0, %1}, %2;" : "=f"(lo), "=f"(hi) : "l"(a));
    return lo + hi;
}
__device__ __forceinline__ float tanh_hw(float x) {
    float y;
    asm("tanh.approx.f32 %0, %1;" : "=f"(y) : "f"(x));
    return y;
}
__device__ __forceinline__ float sigm(float x) {
    return fmaf(0.5f, tanh_hw(0.5f * x), 0.5f);
}

// acc[g][r] += W(5 gate-rows, 16 k's) . X(8 rows, 16 k's)
__device__ __forceinline__ void gemm_sideB(const float* __restrict__ wbase,
                                           const float* __restrict__ hbase,
                                           unsigned long long acc[5][8]) {
    const ulonglong2* W = (const ulonglong2*)wbase;
    const ulonglong2* H = (const ulonglong2*)hbase;
#pragma unroll
    for (int kq = 0; kq < 4; kq++) {
        ulonglong2 h[8];
#pragma unroll
        for (int r = 0; r < 8; r++) h[r] = H[r * 33 + kq];
#pragma unroll
        for (int g = 0; g < 5; g++) {
            ulonglong2 w = W[g * 33 + kq];
#pragma unroll
            for (int r = 0; r < 8; r++) {
                acc[g][r] = fma2(w.x, h[r].x, acc[g][r]);
                acc[g][r] = fma2(w.y, h[r].y, acc[g][r]);
            }
        }
    }
}

extern "C" __global__ void __launch_bounds__(NTHR, 1)
tac_lstm17(const int*   __restrict__ ids,
           const float* __restrict__ embed,
           const float* __restrict__ whx_w,
           const float* __restrict__ whx_b,
           const float* __restrict__ init_state,
           const float* __restrict__ final_w,
           const float* __restrict__ final_b,
           float*       __restrict__ out)
{
    extern __shared__ float sm[];
    const int tid = threadIdx.x;
    const int bid = blockIdx.x;
    const int cg  = bid & 7;
    const int rg  = bid >> 3;
    const int colbase = cg * 16;
    const int rowbase = rg * 16;

    unsigned* bar  = &g_bar[rg << 6];
    unsigned* done = &g_done[rg << 6];

    // GEMM identity: 16 cols x 2 rowgroups(8 rows) x 8 k-splits(16 k)
    const int col    = tid & 15;
    const int rowgrp = (tid >> 4) & 1;
    const int ks     = tid >> 5;          // warp id
    const int kb     = ks << 4;
    const int r0     = rowgrp << 3;

    // gate identity: gcol fastest (coalesced h stores)
    const int gcol = tid & 15;
    const int grow = tid >> 4;

    // ---- one-time: weights into smem ----
    for (int idx = tid; idx < 80 * 128; idx += NTHR) {
        int k  = idx & 127;
        int j2 = idx >> 7;                 // c*5+g
        int c  = j2 / 5;
        int g  = j2 - 5 * c;
        int jg = (g << 7) + colbase + c;
        sm[OFF_WL + j2 * 132 + k] = whx_w[jg * 256 + k];
        sm[OFF_WR + j2 * 132 + k] = whx_w[jg * 256 + 128 + k];
    }
    if (tid < 80) {
        int c = tid / 5, g = tid - 5 * (tid / 5);
        sm[OFF_SB + tid] = whx_b[(g << 7) + colbase + c];
    }
    // SH(t=0) = init_state broadcast
    for (int idx = tid; idx < 16 * 128; idx += NTHR) {
        int r = idx >> 7, k = idx & 127;
        sm[OFF_SH + r * 132 + k] = init_state[k];
    }
    // gather x(0) -> SX[0], x(1) -> SX[1]
    {
        int r = tid >> 4, l = tid & 15;
#pragma unroll
        for (int tt = 0; tt < 2; tt++) {
            int id = __ldg(&ids[(rowbase + r) * L_ + tt]);
            const float4* eb = (const float4*)(embed + (size_t)id * 256);
            float4 e0 = __ldg(eb + l);
            float4 e1 = __ldg(eb + 16 + l);
            *(float4*)&sm[OFF_SX + tt * SZ_SX + r * 132 + l * 4]      = e0;
            *(float4*)&sm[OFF_SX + tt * SZ_SX + r * 132 + 64 + l * 4] = e1;
        }
    }
    float cstate = init_state[128 + colbase + gcol];
    int   id0    = __ldg(&ids[(rowbase + grow) * L_]);
    float rc_cur = __ldg(&embed[(size_t)id0 * 256 + 128 + colbase + gcol]);
    float rc_next = 0.0f;
    __syncthreads();

    const float* wlq = sm + OFF_WL + col * 5 * 132 + kb;
    const float* wrq = sm + OFF_WR + col * 5 * 132 + kb;
    const int    xro = r0 * 132 + kb;

    unsigned long long acc[5][8];
#pragma unroll
    for (int g = 0; g < 5; g++)
#pragma unroll
        for (int r = 0; r < 8; r++) acc[g][r] = 0ull;

    gemm_sideB(wrq, sm + OFF_SX + xro, acc);   // accR(0)

    // ================= sequential scan =================
    for (int t = 0; t < L_; t++) {
        // ---- load h(t) tile (t>0): [b][k] layout ----
        if (t > 0) {
            const float4* hb = (const float4*)(g_h[t & 1] + rowbase * 128);
            {
                int r  = tid >> 5;             // warp id = row
                int k4 = tid & 31;
                float4 v = __ldcg(hb + r * 32 + k4);
                *(float4*)&sm[OFF_SH + r * 132 + k4 * 4] = v;
                float4 w = __ldcg(hb + (r + 8) * 32 + k4);
                *(float4*)&sm[OFF_SH + (r + 8) * 132 + k4 * 4] = w;
            }
            __syncthreads();
        }

        // ---- accL(t) on top of accR(t) ----
        gemm_sideB(wlq, sm + OFF_SH + xro, acc);

        // ---- store z partials (this k-split's slice) ----
        {
            float* zb = sm + OFF_ZB + ks * SZ_ZB + col * 5;
#pragma unroll
            for (int g = 0; g < 5; g++)
#pragma unroll
                for (int r = 0; r < 8; r++)
                    zb[(r0 + r) * 84 + g] = hadd2(acc[g][r]);
        }
        __syncthreads();

        // ---- gate phase: reduce 8 k-split partials ----
        {
            const float* z0 = sm + OFF_ZB + grow * 84 + gcol * 5;
            float z[5];
#pragma unroll
            for (int g = 0; g < 5; g++) {
                float s = sm[OFF_SB + gcol * 5 + g];
#pragma unroll
                for (int p = 0; p < 8; p++) s += z0[p * SZ_ZB + g];
                z[g] = s;
            }
            float ta  = tanh_hw(z[0]);
            float si  = sigm(z[1]);
            float sf1 = sigm(z[2]);
            float sf2 = sigm(z[3]);
            float so  = sigm(z[4]);
            cstate = ta * si + sf1 * cstate + sf2 * rc_cur;
            float hval = so * tanh_hw(cstate);
            __stcg(&g_h[(t + 1) & 1][(rowbase + grow) * 128 + colbase + gcol], hval);
        }

        __syncthreads();
        if (tid == 0) {
            asm volatile("red.release.gpu.global.add.u32 [%0], %1;"
                         :: "l"(bar), "r"(1u) : "memory");
        }

        // ---- shadow: right GEMM for t+1, gather x(t+2), rc(t+1) ----
#pragma unroll
        for (int g = 0; g < 5; g++)
#pragma unroll
            for (int r = 0; r < 8; r++) acc[g][r] = 0ull;

        if (t < L_ - 1) {
            int idn = __ldg(&ids[(rowbase + grow) * L_ + t + 1]);
            rc_next = __ldg(&embed[(size_t)idn * 256 + 128 + colbase + gcol]);
            gemm_sideB(wrq, sm + OFF_SX + ((t + 1) & 1) * SZ_SX + xro, acc);
        }
        if (t < L_ - 2) {
            int r = tid >> 4, l = tid & 15;
            int id = __ldg(&ids[(rowbase + r) * L_ + t + 2]);
            const float4* eb = (const float4*)(embed + (size_t)id * 256);
            float4 e0 = __ldg(eb + l);
            float4 e1 = __ldg(eb + 16 + l);
            *(float4*)&sm[OFF_SX + (t & 1) * SZ_SX + r * 132 + l * 4]      = e0;
            *(float4*)&sm[OFF_SX + (t & 1) * SZ_SX + r * 132 + 64 + l * 4] = e1;
        }

        // ---- all threads poll (identical addr -> one L2 req/warp) ----
        {
            unsigned tgt = 8u * (unsigned)(t + 1);
            unsigned v;
            do {
                asm volatile("ld.acquire.gpu.global.u32 %0, [%1];"
                             : "=r"(v) : "l"(bar) : "memory");
            } while (v < tgt);
        }
        rc_cur = rc_next;
    }

    // ================= final projection (cg==0 blocks) =================
    if (cg == 0) {
        int r2 = tid >> 4;
        int l2 = tid & 15;
        const float* hrow = g_h[0] + (rowbase + r2) * 128;
        float p0 = 0.f, p1 = 0.f, p2 = 0.f;
#pragma unroll
        for (int i = 0; i < 8; i++) {
            int k = l2 * 8 + i;
            float hv = __ldcg(&hrow[k]);
            p0 = fmaf(hv, __ldg(&final_w[k]),       p0);
            p1 = fmaf(hv, __ldg(&final_w[128 + k]), p1);
            p2 = fmaf(hv, __ldg(&final_w[256 + k]), p2);
        }
#pragma unroll
        for (int off = 8; off > 0; off >>= 1) {
            p0 += __shfl_down_sync(0xffffffffu, p0, off, 16);
            p1 += __shfl_down_sync(0xffffffffu, p1, off, 16);
            p2 += __shfl_down_sync(0xffffffffu, p2, off, 16);
        }
        if (l2 == 0) {
            int b = rowbase + r2;
            out[b * 3 + 0] = p0 + __ldg(&final_b[0]);
            out[b * 3 + 1] = p1 + __ldg(&final_b[1]);
            out[b * 3 + 2] = p2 + __ldg(&final_b[2]);
        }
    }

    // ---- reset this rg's counters for next graph replay ----
    __threadfence();
    __syncthreads();
    if (tid == 0) {
        unsigned v = atomicAdd(done, 1u);
        if (v == 7u) {
            *bar  = 0u;
            *done = 0u;
            __threadfence();
        }
    }
}

extern "C" void kernel_launch(void* const* d_in, const int* in_sizes, int n_in,
                              void* d_out, int out_size)
{
    const int*   ids        = nullptr;
    const float* embed      = nullptr;
    const float* whx_w      = nullptr;
    const float* whx_b      = nullptr;
    const float* init_state = nullptr;
    const float* final_w    = nullptr;
    const float* final_b    = nullptr;
    for (int i = 0; i < n_in; i++) {
        switch (in_sizes[i]) {
            case 256 * 128:   ids        = (const int*)d_in[i];   break;
            case 50000 * 256: embed      = (const float*)d_in[i]; break;
            case 640 * 256:   whx_w      = (const float*)d_in[i]; break;
            case 640:         whx_b      = (const float*)d_in[i]; break;
            case 256:         init_state = (const float*)d_in[i]; break;
            case 3 * 128:     final_w    = (const float*)d_in[i]; break;
            case 3:           final_b    = (const float*)d_in[i]; break;
            default: break;
        }
    }
    float* out = (float*)d_out;

    cudaFuncSetAttribute(tac_lstm17,
                         cudaFuncAttributeMaxDynamicSharedMemorySize, SMEM_BYTES);
    tac_lstm17<<<NBLK, NTHR, SMEM_BYTES>>>(ids, embed, whx_w, whx_b,
                                           init_state, final_w, final_b, out);
}